// round 1
// baseline (speedup 1.0000x reference)
#include <cuda_runtime.h>
#include <cstdint>

#define RR 10
#define BLOCK 128

// S table: [k=u/2][a][a2] as float2 = (S[2k,a,a2], S[2k+1,a,a2])
__device__ __align__(16) float2 S2g[16 * 16 * 16];
__device__ unsigned int g_ticket;

// ---------------------------------------------------------------------------
// Precompute kernel: one block per unit u (32 blocks, 256 threads).
// Builds the 16x16 bilinear-form matrix S_u from the tree cores + factors.
// ---------------------------------------------------------------------------
__global__ void precompute_S(const float* __restrict__ core11,
                             const float* __restrict__ core12,
                             const float* __restrict__ core13,
                             const float* __restrict__ core14,
                             const float* __restrict__ core21,
                             const float* __restrict__ core22,
                             const float* __restrict__ FM,   // [2][10][8][32]
                             const float* __restrict__ MT)   // [10][10]
{
    __shared__ float v[8][2][RR];        // leaf basis vectors
    __shared__ float WP[4][2][RR][RR];   // partial: sum_i v0[i]*core1[i,k,j]
    __shared__ float P[4][4][RR];        // level-1 basis
    __shared__ float W2[2][4][RR][RR];   // partial: sum_i P[c1][i]*core2[i,k,j]
    __shared__ float Q[2][16][RR];       // level-2 basis
    __shared__ float QT[16][RR];         // Q1 @ MT

    const int u = blockIdx.x;
    const int tid = threadIdx.x;

    if (u == 0 && tid == 0) g_ticket = 0u;   // reset ticket for main kernel

    // v[f][d][r] = FM[((d*10+r)*8+f)*32 + u]
    for (int idx = tid; idx < 8 * 2 * RR; idx += blockDim.x) {
        int f = idx / (2 * RR);
        int d = (idx / RR) & 1;
        int r = idx % RR;
        v[f][d][r] = FM[((d * RR + r) * 8 + f) * 32 + u];
    }
    __syncthreads();

    const float* cores1[4] = {core11, core12, core13, core14};

    // WP[p][al][k][j] = sum_i v[2p][al][i] * core1p[i,k,j]
    for (int idx = tid; idx < 800; idx += blockDim.x) {
        int p  = idx / 200;
        int al = (idx / 100) & 1;
        int k  = (idx / RR) % RR;
        int j  = idx % RR;
        const float* core = cores1[p];
        float s = 0.f;
        #pragma unroll
        for (int i = 0; i < RR; i++)
            s += v[2 * p][al][i] * __ldg(&core[(i * RR + k) * RR + j]);
        WP[p][al][k][j] = s;
    }
    __syncthreads();

    // P[p][c=al*2+be][j] = sum_k v[2p+1][be][k] * WP[p][al][k][j]
    for (int idx = tid; idx < 160; idx += blockDim.x) {
        int p = idx / 40;
        int c = (idx / RR) & 3;
        int j = idx % RR;
        int al = c >> 1, be = c & 1;
        float s = 0.f;
        #pragma unroll
        for (int k = 0; k < RR; k++)
            s += v[2 * p + 1][be][k] * WP[p][al][k][j];
        P[p][c][j] = s;
    }
    __syncthreads();

    // W2[t][c1][k][j] = sum_i P[2t][c1][i] * core2t[i,k,j]
    for (int idx = tid; idx < 800; idx += blockDim.x) {
        int t  = idx / 400;
        int c1 = (idx / 100) & 3;
        int k  = (idx / RR) % RR;
        int j  = idx % RR;
        const float* core = t ? core22 : core21;
        float s = 0.f;
        #pragma unroll
        for (int i = 0; i < RR; i++)
            s += P[2 * t][c1][i] * __ldg(&core[(i * RR + k) * RR + j]);
        W2[t][c1][k][j] = s;
    }
    __syncthreads();

    // Q[t][a=c1*4+c2][j] = sum_k P[2t+1][c2][k] * W2[t][c1][k][j]
    for (int idx = tid; idx < 320; idx += blockDim.x) {
        int t = idx / 160;
        int a = (idx / RR) % 16;
        int j = idx % RR;
        int c1 = a >> 2, c2 = a & 3;
        float s = 0.f;
        #pragma unroll
        for (int k = 0; k < RR; k++)
            s += P[2 * t + 1][c2][k] * W2[t][c1][k][j];
        Q[t][a][j] = s;
    }
    __syncthreads();

    // QT[a][j] = sum_i Q1[a][i] * MT[i][j]
    for (int idx = tid; idx < 160; idx += blockDim.x) {
        int a = idx / RR, j = idx % RR;
        float s = 0.f;
        #pragma unroll
        for (int i = 0; i < RR; i++)
            s += Q[0][a][i] * __ldg(&MT[i * RR + j]);
        QT[a][j] = s;
    }
    __syncthreads();

    // S[u][a][a2] = sum_j QT[a][j] * Q2[a2][j]; write half of (2k,2k+1) pair
    for (int idx = tid; idx < 256; idx += blockDim.x) {
        int a = idx >> 4, a2 = idx & 15;
        float s = 0.f;
        #pragma unroll
        for (int j = 0; j < RR; j++)
            s += QT[a][j] * Q[1][a2][j];
        float* dst = reinterpret_cast<float*>(&S2g[((u >> 1) * 16 + a) * 16 + a2]);
        dst[u & 1] = s;
    }
}

// ---------------------------------------------------------------------------
// Main kernel: out[b,u] = mon1(b)^T * S_u * mon2(b), packed f32x2 over (2k,2k+1)
// ---------------------------------------------------------------------------
__device__ __forceinline__ unsigned long long pack2(float lo, float hi) {
    unsigned long long r;
    asm("mov.b64 %0, {%1, %2};" : "=l"(r) : "f"(lo), "f"(hi));
    return r;
}
__device__ __forceinline__ unsigned long long fma2(unsigned long long a,
                                                   unsigned long long b,
                                                   unsigned long long c) {
    unsigned long long d;
    asm("fma.rn.f32x2 %0, %1, %2, %3;" : "=l"(d) : "l"(a), "l"(b), "l"(c));
    return d;
}

__global__ __launch_bounds__(BLOCK) void tree_main(const float* __restrict__ X,
                                                   float* __restrict__ out,
                                                   int ntiles)
{
    __shared__ __align__(16) float2 sS[16 * 16 * 16];   // 32KB
    __shared__ unsigned int sTile;

    {   // stage S into smem (float4 = 2 pairs per load)
        const float4* src = reinterpret_cast<const float4*>(S2g);
        float4* dst = reinterpret_cast<float4*>(sS);
        for (int i = threadIdx.x; i < 16 * 16 * 16 / 2; i += BLOCK) dst[i] = src[i];
    }
    __syncthreads();

    while (true) {
        if (threadIdx.x == 0) sTile = atomicAdd(&g_ticket, 1u);
        __syncthreads();
        unsigned int tile = sTile;
        __syncthreads();
        if (tile >= (unsigned)ntiles) break;

        int b = (int)tile * BLOCK + threadIdx.x;

        // X[b] = 16 contiguous floats: (f,d) pairs
        const float4* xp = reinterpret_cast<const float4*>(X + (size_t)b * 16);
        float4 x0 = xp[0], x1 = xp[1], x2 = xp[2], x3 = xp[3];

        // pair monomials m[c = alpha*2 + beta] = X[leafA,alpha]*X[leafB,beta]
        float m01[4], m23[4], m45[4], m67[4];
        m01[0] = x0.x * x0.z; m01[1] = x0.x * x0.w; m01[2] = x0.y * x0.z; m01[3] = x0.y * x0.w;
        m23[0] = x1.x * x1.z; m23[1] = x1.x * x1.w; m23[2] = x1.y * x1.z; m23[3] = x1.y * x1.w;
        m45[0] = x2.x * x2.z; m45[1] = x2.x * x2.w; m45[2] = x2.y * x2.z; m45[3] = x2.y * x2.w;
        m67[0] = x3.x * x3.z; m67[1] = x3.x * x3.w; m67[2] = x3.y * x3.z; m67[3] = x3.y * x3.w;

        unsigned long long mon1[16], mon2[16];
        #pragma unroll
        for (int c1 = 0; c1 < 4; c1++)
            #pragma unroll
            for (int c2 = 0; c2 < 4; c2++) {
                float a = m01[c1] * m23[c2];
                float b2 = m45[c1] * m67[c2];
                mon1[c1 * 4 + c2] = pack2(a, a);
                mon2[c1 * 4 + c2] = pack2(b2, b2);
            }

        float2* orow = reinterpret_cast<float2*>(out + (size_t)b * 32);
        #pragma unroll 1
        for (int k = 0; k < 16; k++) {
            unsigned long long acc = 0ull;
            const float4* sk = reinterpret_cast<const float4*>(sS) + k * 128;
            #pragma unroll
            for (int a = 0; a < 16; a++) {
                unsigned long long tmp = 0ull;
                const float4* row = sk + a * 8;
                #pragma unroll
                for (int q = 0; q < 8; q++) {
                    float4 sv = row[q];
                    tmp = fma2(pack2(sv.x, sv.y), mon2[2 * q],     tmp);
                    tmp = fma2(pack2(sv.z, sv.w), mon2[2 * q + 1], tmp);
                }
                acc = fma2(tmp, mon1[a], acc);
            }
            orow[k] = *reinterpret_cast<float2*>(&acc);  // out[b,2k], out[b,2k+1]
        }
        __syncthreads();
    }
}

// ---------------------------------------------------------------------------
extern "C" void kernel_launch(void* const* d_in, const int* in_sizes, int n_in,
                              void* d_out, int out_size)
{
    const float* X   = (const float*)d_in[0];
    const float* c11 = (const float*)d_in[1];
    const float* c12 = (const float*)d_in[2];
    const float* c13 = (const float*)d_in[3];
    const float* c14 = (const float*)d_in[4];
    const float* c21 = (const float*)d_in[5];
    const float* c22 = (const float*)d_in[6];
    const float* FM  = (const float*)d_in[7];
    const float* MT  = (const float*)d_in[8];
    (void)n_in; (void)out_size;

    int B = in_sizes[0] / 16;          // X is [B, 8, 2]
    int ntiles = B / BLOCK;            // 512 for B=65536

    precompute_S<<<32, 256>>>(c11, c12, c13, c14, c21, c22, FM, MT);
    tree_main<<<444, BLOCK>>>(X, (float*)d_out, ntiles);
}

// round 2
// speedup vs baseline: 1.0310x; 1.0310x over previous
#include <cuda_runtime.h>
#include <cstdint>

#define RR 10
#define BLOCK 128
#define GB 2                 // batches per thread
#define TILE (BLOCK * GB)    // 256 batches per tile

// S table: [k=u/2][a][a2] as float2 = (S[2k,a,a2], S[2k+1,a,a2])
__device__ __align__(16) float2 S2g[16 * 16 * 16];
__device__ unsigned int g_ticket;

// ---------------------------------------------------------------------------
// Precompute kernel: one block per unit u (32 blocks, 256 threads).
// ---------------------------------------------------------------------------
__global__ void precompute_S(const float* __restrict__ core11,
                             const float* __restrict__ core12,
                             const float* __restrict__ core13,
                             const float* __restrict__ core14,
                             const float* __restrict__ core21,
                             const float* __restrict__ core22,
                             const float* __restrict__ FM,   // [2][10][8][32]
                             const float* __restrict__ MT)   // [10][10]
{
    __shared__ float v[8][2][RR];
    __shared__ float WP[4][2][RR][RR];
    __shared__ float P[4][4][RR];
    __shared__ float W2[2][4][RR][RR];
    __shared__ float Q[2][16][RR];
    __shared__ float QT[16][RR];

    const int u = blockIdx.x;
    const int tid = threadIdx.x;

    if (u == 0 && tid == 0) g_ticket = 0u;

    for (int idx = tid; idx < 8 * 2 * RR; idx += blockDim.x) {
        int f = idx / (2 * RR);
        int d = (idx / RR) & 1;
        int r = idx % RR;
        v[f][d][r] = FM[((d * RR + r) * 8 + f) * 32 + u];
    }
    __syncthreads();

    const float* cores1[4] = {core11, core12, core13, core14};

    for (int idx = tid; idx < 800; idx += blockDim.x) {
        int p  = idx / 200;
        int al = (idx / 100) & 1;
        int k  = (idx / RR) % RR;
        int j  = idx % RR;
        const float* core = cores1[p];
        float s = 0.f;
        #pragma unroll
        for (int i = 0; i < RR; i++)
            s += v[2 * p][al][i] * __ldg(&core[(i * RR + k) * RR + j]);
        WP[p][al][k][j] = s;
    }
    __syncthreads();

    for (int idx = tid; idx < 160; idx += blockDim.x) {
        int p = idx / 40;
        int c = (idx / RR) & 3;
        int j = idx % RR;
        int al = c >> 1, be = c & 1;
        float s = 0.f;
        #pragma unroll
        for (int k = 0; k < RR; k++)
            s += v[2 * p + 1][be][k] * WP[p][al][k][j];
        P[p][c][j] = s;
    }
    __syncthreads();

    for (int idx = tid; idx < 800; idx += blockDim.x) {
        int t  = idx / 400;
        int c1 = (idx / 100) & 3;
        int k  = (idx / RR) % RR;
        int j  = idx % RR;
        const float* core = t ? core22 : core21;
        float s = 0.f;
        #pragma unroll
        for (int i = 0; i < RR; i++)
            s += P[2 * t][c1][i] * __ldg(&core[(i * RR + k) * RR + j]);
        W2[t][c1][k][j] = s;
    }
    __syncthreads();

    for (int idx = tid; idx < 320; idx += blockDim.x) {
        int t = idx / 160;
        int a = (idx / RR) % 16;
        int j = idx % RR;
        int c1 = a >> 2, c2 = a & 3;
        float s = 0.f;
        #pragma unroll
        for (int k = 0; k < RR; k++)
            s += P[2 * t + 1][c2][k] * W2[t][c1][k][j];
        Q[t][a][j] = s;
    }
    __syncthreads();

    for (int idx = tid; idx < 160; idx += blockDim.x) {
        int a = idx / RR, j = idx % RR;
        float s = 0.f;
        #pragma unroll
        for (int i = 0; i < RR; i++)
            s += Q[0][a][i] * __ldg(&MT[i * RR + j]);
        QT[a][j] = s;
    }
    __syncthreads();

    for (int idx = tid; idx < 256; idx += blockDim.x) {
        int a = idx >> 4, a2 = idx & 15;
        float s = 0.f;
        #pragma unroll
        for (int j = 0; j < RR; j++)
            s += QT[a][j] * Q[1][a2][j];
        float* dst = reinterpret_cast<float*>(&S2g[((u >> 1) * 16 + a) * 16 + a2]);
        dst[u & 1] = s;
    }
}

// ---------------------------------------------------------------------------
// f32x2 helpers
// ---------------------------------------------------------------------------
__device__ __forceinline__ unsigned long long pack2(float lo, float hi) {
    unsigned long long r;
    asm("mov.b64 %0, {%1, %2};" : "=l"(r) : "f"(lo), "f"(hi));
    return r;
}
__device__ __forceinline__ unsigned long long fma2(unsigned long long a,
                                                   unsigned long long b,
                                                   unsigned long long c) {
    unsigned long long d;
    asm("fma.rn.f32x2 %0, %1, %2, %3;" : "=l"(d) : "l"(a), "l"(b), "l"(c));
    return d;
}

// ---------------------------------------------------------------------------
// Main kernel: out[b,u] = mon1(b)^T * S_u * mon2(b)
// f32x2 packed over u-pairs; G=2 batches per thread so each S load feeds 4 FMA2.
// ---------------------------------------------------------------------------
__device__ __forceinline__ void make_mons(const float* __restrict__ X, int b,
                                          unsigned long long* mon1,
                                          unsigned long long* mon2)
{
    const float4* xp = reinterpret_cast<const float4*>(X + (size_t)b * 16);
    float4 x0 = xp[0], x1 = xp[1], x2 = xp[2], x3 = xp[3];

    float m01[4], m23[4], m45[4], m67[4];
    m01[0] = x0.x * x0.z; m01[1] = x0.x * x0.w; m01[2] = x0.y * x0.z; m01[3] = x0.y * x0.w;
    m23[0] = x1.x * x1.z; m23[1] = x1.x * x1.w; m23[2] = x1.y * x1.z; m23[3] = x1.y * x1.w;
    m45[0] = x2.x * x2.z; m45[1] = x2.x * x2.w; m45[2] = x2.y * x2.z; m45[3] = x2.y * x2.w;
    m67[0] = x3.x * x3.z; m67[1] = x3.x * x3.w; m67[2] = x3.y * x3.z; m67[3] = x3.y * x3.w;

    #pragma unroll
    for (int c1 = 0; c1 < 4; c1++)
        #pragma unroll
        for (int c2 = 0; c2 < 4; c2++) {
            float a  = m01[c1] * m23[c2];
            float b2 = m45[c1] * m67[c2];
            mon1[c1 * 4 + c2] = pack2(a, a);
            mon2[c1 * 4 + c2] = pack2(b2, b2);
        }
}

__global__ __launch_bounds__(BLOCK, 3) void tree_main(const float* __restrict__ X,
                                                      float* __restrict__ out,
                                                      int ntiles)
{
    __shared__ __align__(16) float2 sS[16 * 16 * 16];   // 32KB
    __shared__ unsigned int sTile;

    {   // stage S into smem
        const float4* src = reinterpret_cast<const float4*>(S2g);
        float4* dst = reinterpret_cast<float4*>(sS);
        for (int i = threadIdx.x; i < 16 * 16 * 16 / 2; i += BLOCK) dst[i] = src[i];
    }
    __syncthreads();

    while (true) {
        if (threadIdx.x == 0) sTile = atomicAdd(&g_ticket, 1u);
        __syncthreads();
        unsigned int tile = sTile;
        __syncthreads();
        if (tile >= (unsigned)ntiles) break;

        int b0 = (int)tile * TILE + threadIdx.x;          // batch A
        int b1 = b0 + BLOCK;                              // batch B

        unsigned long long mon1A[16], mon2A[16];
        unsigned long long mon1B[16], mon2B[16];
        make_mons(X, b0, mon1A, mon2A);
        make_mons(X, b1, mon1B, mon2B);

        float2* orowA = reinterpret_cast<float2*>(out + (size_t)b0 * 32);
        float2* orowB = reinterpret_cast<float2*>(out + (size_t)b1 * 32);

        #pragma unroll 1
        for (int k = 0; k < 16; k++) {
            unsigned long long accA = 0ull, accB = 0ull;
            const float4* sk = reinterpret_cast<const float4*>(sS) + k * 128;
            #pragma unroll
            for (int a = 0; a < 16; a++) {
                unsigned long long tA = 0ull, tB = 0ull;
                const float4* row = sk + a * 8;
                #pragma unroll
                for (int q = 0; q < 8; q++) {
                    float4 sv = row[q];
                    unsigned long long s01 = pack2(sv.x, sv.y);
                    unsigned long long s23 = pack2(sv.z, sv.w);
                    tA = fma2(s01, mon2A[2 * q],     tA);
                    tA = fma2(s23, mon2A[2 * q + 1], tA);
                    tB = fma2(s01, mon2B[2 * q],     tB);
                    tB = fma2(s23, mon2B[2 * q + 1], tB);
                }
                accA = fma2(tA, mon1A[a], accA);
                accB = fma2(tB, mon1B[a], accB);
            }
            orowA[k] = *reinterpret_cast<float2*>(&accA);
            orowB[k] = *reinterpret_cast<float2*>(&accB);
        }
        __syncthreads();
    }
}

// ---------------------------------------------------------------------------
extern "C" void kernel_launch(void* const* d_in, const int* in_sizes, int n_in,
                              void* d_out, int out_size)
{
    const float* X   = (const float*)d_in[0];
    const float* c11 = (const float*)d_in[1];
    const float* c12 = (const float*)d_in[2];
    const float* c13 = (const float*)d_in[3];
    const float* c14 = (const float*)d_in[4];
    const float* c21 = (const float*)d_in[5];
    const float* c22 = (const float*)d_in[6];
    const float* FM  = (const float*)d_in[7];
    const float* MT  = (const float*)d_in[8];
    (void)n_in; (void)out_size;

    int B = in_sizes[0] / 16;          // X is [B, 8, 2]
    int ntiles = B / TILE;             // 256 for B=65536

    precompute_S<<<32, 256>>>(c11, c12, c13, c14, c21, c22, FM, MT);
    tree_main<<<444, BLOCK>>>(X, (float*)d_out, ntiles);
}

// round 3
// speedup vs baseline: 1.2252x; 1.1884x over previous
#include <cuda_runtime.h>
#include <cstdint>

#define RR 10
#define BLOCK 128

typedef unsigned long long ull;

// S table: [k=u/2][a][a2] as float2 = (S[2k,a,a2], S[2k+1,a,a2])
__device__ __align__(16) float2 S2g[16 * 16 * 16];

// ---------------------------------------------------------------------------
// Precompute kernel: one block per unit u (32 blocks, 256 threads).
// ---------------------------------------------------------------------------
__global__ void precompute_S(const float* __restrict__ core11,
                             const float* __restrict__ core12,
                             const float* __restrict__ core13,
                             const float* __restrict__ core14,
                             const float* __restrict__ core21,
                             const float* __restrict__ core22,
                             const float* __restrict__ FM,   // [2][10][8][32]
                             const float* __restrict__ MT)   // [10][10]
{
    __shared__ float v[8][2][RR];
    __shared__ float WP[4][2][RR][RR];
    __shared__ float P[4][4][RR];
    __shared__ float W2[2][4][RR][RR];
    __shared__ float Q[2][16][RR];
    __shared__ float QT[16][RR];

    const int u = blockIdx.x;
    const int tid = threadIdx.x;

    for (int idx = tid; idx < 8 * 2 * RR; idx += blockDim.x) {
        int f = idx / (2 * RR);
        int d = (idx / RR) & 1;
        int r = idx % RR;
        v[f][d][r] = FM[((d * RR + r) * 8 + f) * 32 + u];
    }
    __syncthreads();

    const float* cores1[4] = {core11, core12, core13, core14};

    for (int idx = tid; idx < 800; idx += blockDim.x) {
        int p  = idx / 200;
        int al = (idx / 100) & 1;
        int k  = (idx / RR) % RR;
        int j  = idx % RR;
        const float* core = cores1[p];
        float s = 0.f;
        #pragma unroll
        for (int i = 0; i < RR; i++)
            s += v[2 * p][al][i] * __ldg(&core[(i * RR + k) * RR + j]);
        WP[p][al][k][j] = s;
    }
    __syncthreads();

    for (int idx = tid; idx < 160; idx += blockDim.x) {
        int p = idx / 40;
        int c = (idx / RR) & 3;
        int j = idx % RR;
        int al = c >> 1, be = c & 1;
        float s = 0.f;
        #pragma unroll
        for (int k = 0; k < RR; k++)
            s += v[2 * p + 1][be][k] * WP[p][al][k][j];
        P[p][c][j] = s;
    }
    __syncthreads();

    for (int idx = tid; idx < 800; idx += blockDim.x) {
        int t  = idx / 400;
        int c1 = (idx / 100) & 3;
        int k  = (idx / RR) % RR;
        int j  = idx % RR;
        const float* core = t ? core22 : core21;
        float s = 0.f;
        #pragma unroll
        for (int i = 0; i < RR; i++)
            s += P[2 * t][c1][i] * __ldg(&core[(i * RR + k) * RR + j]);
        W2[t][c1][k][j] = s;
    }
    __syncthreads();

    for (int idx = tid; idx < 320; idx += blockDim.x) {
        int t = idx / 160;
        int a = (idx / RR) % 16;
        int j = idx % RR;
        int c1 = a >> 2, c2 = a & 3;
        float s = 0.f;
        #pragma unroll
        for (int k = 0; k < RR; k++)
            s += P[2 * t + 1][c2][k] * W2[t][c1][k][j];
        Q[t][a][j] = s;
    }
    __syncthreads();

    for (int idx = tid; idx < 160; idx += blockDim.x) {
        int a = idx / RR, j = idx % RR;
        float s = 0.f;
        #pragma unroll
        for (int i = 0; i < RR; i++)
            s += Q[0][a][i] * __ldg(&MT[i * RR + j]);
        QT[a][j] = s;
    }
    __syncthreads();

    for (int idx = tid; idx < 256; idx += blockDim.x) {
        int a = idx >> 4, a2 = idx & 15;
        float s = 0.f;
        #pragma unroll
        for (int j = 0; j < RR; j++)
            s += QT[a][j] * Q[1][a2][j];
        float* dst = reinterpret_cast<float*>(&S2g[((u >> 1) * 16 + a) * 16 + a2]);
        dst[u & 1] = s;
    }
}

// ---------------------------------------------------------------------------
// f32x2 helpers
// ---------------------------------------------------------------------------
__device__ __forceinline__ ull pack2(float lo, float hi) {
    ull r;
    asm("mov.b64 %0, {%1, %2};" : "=l"(r) : "f"(lo), "f"(hi));
    return r;
}
__device__ __forceinline__ ull fma2(ull a, ull b, ull c) {
    ull d;
    asm("fma.rn.f32x2 %0, %1, %2, %3;" : "=l"(d) : "l"(a), "l"(b), "l"(c));
    return d;
}

// ---------------------------------------------------------------------------
// Main kernel: each thread computes one batch x one k-group (4 u-pairs = 8 units).
// Block = 128 threads, all on the same k-group -> only 8KB of S in smem.
// Grid = (B/128) * 4.
// ---------------------------------------------------------------------------
__global__ __launch_bounds__(BLOCK, 5) void tree_main(const float* __restrict__ X,
                                                      float* __restrict__ out)
{
    __shared__ __align__(16) ulonglong2 sS[512];   // 8KB: [k=0..3][a=0..15][q=0..7]

    const int kg   = blockIdx.x & 3;        // k-group: u-pairs kg*4 .. kg*4+3
    const int bblk = blockIdx.x >> 2;

    {   // stage this k-group's S slice: 4 u-pairs x 256 float2 = 8KB contiguous
        const ulonglong2* src = reinterpret_cast<const ulonglong2*>(S2g) + kg * 512;
        #pragma unroll
        for (int i = 0; i < 4; i++)
            sS[threadIdx.x + i * BLOCK] = src[threadIdx.x + i * BLOCK];
    }
    __syncthreads();

    const int b = bblk * BLOCK + threadIdx.x;

    // ---- monomials ----
    const float4* xp = reinterpret_cast<const float4*>(X + (size_t)b * 16);
    float4 x0 = xp[0], x1 = xp[1], x2 = xp[2], x3 = xp[3];

    float m01[4], m23[4], m45[4], m67[4];
    m01[0] = x0.x * x0.z; m01[1] = x0.x * x0.w; m01[2] = x0.y * x0.z; m01[3] = x0.y * x0.w;
    m23[0] = x1.x * x1.z; m23[1] = x1.x * x1.w; m23[2] = x1.y * x1.z; m23[3] = x1.y * x1.w;
    m45[0] = x2.x * x2.z; m45[1] = x2.x * x2.w; m45[2] = x2.y * x2.z; m45[3] = x2.y * x2.w;
    m67[0] = x3.x * x3.z; m67[1] = x3.x * x3.w; m67[2] = x3.y * x3.z; m67[3] = x3.y * x3.w;

    float mon1[16];            // scalar; packed per use (16 movs total)
    ull   mon2[16];            // duplicated-pair packed
    #pragma unroll
    for (int c1 = 0; c1 < 4; c1++)
        #pragma unroll
        for (int c2 = 0; c2 < 4; c2++) {
            mon1[c1 * 4 + c2] = m01[c1] * m23[c2];
            float b2 = m45[c1] * m67[c2];
            mon2[c1 * 4 + c2] = pack2(b2, b2);
        }

    // ---- bilinear forms: 4 independent accumulator chains (one per u-pair) ----
    ull acc0 = 0ull, acc1 = 0ull, acc2 = 0ull, acc3 = 0ull;

    #pragma unroll 2
    for (int a = 0; a < 16; a++) {
        ull m1 = pack2(mon1[a], mon1[a]);
        ull t0 = 0ull, t1 = 0ull, t2 = 0ull, t3 = 0ull;
        const ulonglong2* r0 = sS + (0 * 16 + a) * 8;
        const ulonglong2* r1 = sS + (1 * 16 + a) * 8;
        const ulonglong2* r2 = sS + (2 * 16 + a) * 8;
        const ulonglong2* r3 = sS + (3 * 16 + a) * 8;
        #pragma unroll
        for (int q = 0; q < 8; q++) {
            ulonglong2 s0 = r0[q];
            ulonglong2 s1 = r1[q];
            ulonglong2 s2 = r2[q];
            ulonglong2 s3 = r3[q];
            ull ma = mon2[2 * q], mb = mon2[2 * q + 1];
            t0 = fma2(s0.x, ma, t0); t0 = fma2(s0.y, mb, t0);
            t1 = fma2(s1.x, ma, t1); t1 = fma2(s1.y, mb, t1);
            t2 = fma2(s2.x, ma, t2); t2 = fma2(s2.y, mb, t2);
            t3 = fma2(s3.x, ma, t3); t3 = fma2(s3.y, mb, t3);
        }
        acc0 = fma2(t0, m1, acc0);
        acc1 = fma2(t1, m1, acc1);
        acc2 = fma2(t2, m1, acc2);
        acc3 = fma2(t3, m1, acc3);
    }

    // out[b, kg*8 .. kg*8+7] : two 16B stores
    ulonglong2* orow = reinterpret_cast<ulonglong2*>(out + (size_t)b * 32 + kg * 8);
    ulonglong2 o0; o0.x = acc0; o0.y = acc1;
    ulonglong2 o1; o1.x = acc2; o1.y = acc3;
    orow[0] = o0;
    orow[1] = o1;
}

// ---------------------------------------------------------------------------
extern "C" void kernel_launch(void* const* d_in, const int* in_sizes, int n_in,
                              void* d_out, int out_size)
{
    const float* X   = (const float*)d_in[0];
    const float* c11 = (const float*)d_in[1];
    const float* c12 = (const float*)d_in[2];
    const float* c13 = (const float*)d_in[3];
    const float* c14 = (const float*)d_in[4];
    const float* c21 = (const float*)d_in[5];
    const float* c22 = (const float*)d_in[6];
    const float* FM  = (const float*)d_in[7];
    const float* MT  = (const float*)d_in[8];
    (void)n_in; (void)out_size;

    int B = in_sizes[0] / 16;          // X is [B, 8, 2]
    int nbblk = B / BLOCK;             // 512 for B=65536

    precompute_S<<<32, 256>>>(c11, c12, c13, c14, c21, c22, FM, MT);
    tree_main<<<nbblk * 4, BLOCK>>>(X, (float*)d_out);
}

// round 4
// speedup vs baseline: 1.4973x; 1.2221x over previous
#include <cuda_runtime.h>
#include <cstdint>

#define RR 10
#define BLOCK 128

typedef unsigned long long ull;

// S table: [k=u/2][a][a2] as float2 = (S[2k,a,a2], S[2k+1,a,a2])
__device__ __align__(16) float2 S2g[16 * 16 * 16];

// ---------------------------------------------------------------------------
// Precompute kernel: one block per unit u (32 blocks, 256 threads).
// ---------------------------------------------------------------------------
__global__ void precompute_S(const float* __restrict__ core11,
                             const float* __restrict__ core12,
                             const float* __restrict__ core13,
                             const float* __restrict__ core14,
                             const float* __restrict__ core21,
                             const float* __restrict__ core22,
                             const float* __restrict__ FM,   // [2][10][8][32]
                             const float* __restrict__ MT)   // [10][10]
{
    __shared__ float v[8][2][RR];
    __shared__ float WP[4][2][RR][RR];
    __shared__ float P[4][4][RR];
    __shared__ float W2[2][4][RR][RR];
    __shared__ float Q[2][16][RR];
    __shared__ float QT[16][RR];

    const int u = blockIdx.x;
    const int tid = threadIdx.x;

    for (int idx = tid; idx < 8 * 2 * RR; idx += blockDim.x) {
        int f = idx / (2 * RR);
        int d = (idx / RR) & 1;
        int r = idx % RR;
        v[f][d][r] = FM[((d * RR + r) * 8 + f) * 32 + u];
    }
    __syncthreads();

    const float* cores1[4] = {core11, core12, core13, core14};

    for (int idx = tid; idx < 800; idx += blockDim.x) {
        int p  = idx / 200;
        int al = (idx / 100) & 1;
        int k  = (idx / RR) % RR;
        int j  = idx % RR;
        const float* core = cores1[p];
        float s = 0.f;
        #pragma unroll
        for (int i = 0; i < RR; i++)
            s += v[2 * p][al][i] * __ldg(&core[(i * RR + k) * RR + j]);
        WP[p][al][k][j] = s;
    }
    __syncthreads();

    for (int idx = tid; idx < 160; idx += blockDim.x) {
        int p = idx / 40;
        int c = (idx / RR) & 3;
        int j = idx % RR;
        int al = c >> 1, be = c & 1;
        float s = 0.f;
        #pragma unroll
        for (int k = 0; k < RR; k++)
            s += v[2 * p + 1][be][k] * WP[p][al][k][j];
        P[p][c][j] = s;
    }
    __syncthreads();

    for (int idx = tid; idx < 800; idx += blockDim.x) {
        int t  = idx / 400;
        int c1 = (idx / 100) & 3;
        int k  = (idx / RR) % RR;
        int j  = idx % RR;
        const float* core = t ? core22 : core21;
        float s = 0.f;
        #pragma unroll
        for (int i = 0; i < RR; i++)
            s += P[2 * t][c1][i] * __ldg(&core[(i * RR + k) * RR + j]);
        W2[t][c1][k][j] = s;
    }
    __syncthreads();

    for (int idx = tid; idx < 320; idx += blockDim.x) {
        int t = idx / 160;
        int a = (idx / RR) % 16;
        int j = idx % RR;
        int c1 = a >> 2, c2 = a & 3;
        float s = 0.f;
        #pragma unroll
        for (int k = 0; k < RR; k++)
            s += P[2 * t + 1][c2][k] * W2[t][c1][k][j];
        Q[t][a][j] = s;
    }
    __syncthreads();

    for (int idx = tid; idx < 160; idx += blockDim.x) {
        int a = idx / RR, j = idx % RR;
        float s = 0.f;
        #pragma unroll
        for (int i = 0; i < RR; i++)
            s += Q[0][a][i] * __ldg(&MT[i * RR + j]);
        QT[a][j] = s;
    }
    __syncthreads();

    for (int idx = tid; idx < 256; idx += blockDim.x) {
        int a = idx >> 4, a2 = idx & 15;
        float s = 0.f;
        #pragma unroll
        for (int j = 0; j < RR; j++)
            s += QT[a][j] * Q[1][a2][j];
        float* dst = reinterpret_cast<float*>(&S2g[((u >> 1) * 16 + a) * 16 + a2]);
        dst[u & 1] = s;
    }
}

// ---------------------------------------------------------------------------
// f32x2 helpers
// ---------------------------------------------------------------------------
__device__ __forceinline__ ull pack2(float lo, float hi) {
    ull r;
    asm("mov.b64 %0, {%1, %2};" : "=l"(r) : "f"(lo), "f"(hi));
    return r;
}
__device__ __forceinline__ ull fma2(ull a, ull b, ull c) {
    ull d;
    asm("fma.rn.f32x2 %0, %1, %2, %3;" : "=l"(d) : "l"(a), "l"(b), "l"(c));
    return d;
}

// ---------------------------------------------------------------------------
// Main kernel: thread = 2 batches x one k-group of 2 u-pairs (4 units).
// Each S ulonglong2 load feeds 8 FMA2 (2 rows x 2 a2 x 2 batches).
// Block = 128 threads on same k-group -> 4KB S slice in smem.
// Grid = (B/256) * 8.
// ---------------------------------------------------------------------------
__device__ __forceinline__ void make_mons(const float* __restrict__ X, int b,
                                          float* __restrict__ mon1,
                                          ull* __restrict__ mon2)
{
    const float4* xp = reinterpret_cast<const float4*>(X + (size_t)b * 16);
    float4 x0 = xp[0], x1 = xp[1], x2 = xp[2], x3 = xp[3];

    float m01[4], m23[4], m45[4], m67[4];
    m01[0] = x0.x * x0.z; m01[1] = x0.x * x0.w; m01[2] = x0.y * x0.z; m01[3] = x0.y * x0.w;
    m23[0] = x1.x * x1.z; m23[1] = x1.x * x1.w; m23[2] = x1.y * x1.z; m23[3] = x1.y * x1.w;
    m45[0] = x2.x * x2.z; m45[1] = x2.x * x2.w; m45[2] = x2.y * x2.z; m45[3] = x2.y * x2.w;
    m67[0] = x3.x * x3.z; m67[1] = x3.x * x3.w; m67[2] = x3.y * x3.z; m67[3] = x3.y * x3.w;

    #pragma unroll
    for (int c1 = 0; c1 < 4; c1++)
        #pragma unroll
        for (int c2 = 0; c2 < 4; c2++) {
            mon1[c1 * 4 + c2] = m01[c1] * m23[c2];
            float b2 = m45[c1] * m67[c2];
            mon2[c1 * 4 + c2] = pack2(b2, b2);
        }
}

__global__ __launch_bounds__(BLOCK, 4) void tree_main(const float* __restrict__ X,
                                                      float* __restrict__ out)
{
    __shared__ __align__(16) ulonglong2 sS[256];   // 4KB: [r=0..1][a=0..15][q=0..7]

    const int kg   = blockIdx.x & 7;        // k-group: u-pairs kg*2, kg*2+1
    const int bblk = blockIdx.x >> 3;

    {   // stage this k-group's S slice: 2 u-pairs x 256 float2 = 4KB
        const ulonglong2* src = reinterpret_cast<const ulonglong2*>(S2g) + kg * 256;
        sS[threadIdx.x]         = src[threadIdx.x];
        sS[threadIdx.x + BLOCK] = src[threadIdx.x + BLOCK];
    }
    __syncthreads();

    const int b0 = bblk * (2 * BLOCK) + threadIdx.x;   // batch A
    const int b1 = b0 + BLOCK;                          // batch B

    float mon1A[16], mon1B[16];
    ull   mon2A[16], mon2B[16];
    make_mons(X, b0, mon1A, mon2A);
    make_mons(X, b1, mon1B, mon2B);

    // ---- bilinear forms: 8 independent inner chains ----
    ull accA0 = 0ull, accA1 = 0ull, accB0 = 0ull, accB1 = 0ull;

    #pragma unroll 2
    for (int a = 0; a < 16; a++) {
        ull m1A = pack2(mon1A[a], mon1A[a]);
        ull m1B = pack2(mon1B[a], mon1B[a]);
        ull tA0 = 0ull, tA1 = 0ull, tB0 = 0ull, tB1 = 0ull;
        const ulonglong2* r0 = sS + (0 * 16 + a) * 8;
        const ulonglong2* r1 = sS + (1 * 16 + a) * 8;
        #pragma unroll
        for (int q = 0; q < 8; q++) {
            ulonglong2 s0 = r0[q];
            ulonglong2 s1 = r1[q];
            ull ma = mon2A[2 * q], mb = mon2A[2 * q + 1];
            ull mc = mon2B[2 * q], md = mon2B[2 * q + 1];
            tA0 = fma2(s0.x, ma, tA0); tA0 = fma2(s0.y, mb, tA0);
            tB0 = fma2(s0.x, mc, tB0); tB0 = fma2(s0.y, md, tB0);
            tA1 = fma2(s1.x, ma, tA1); tA1 = fma2(s1.y, mb, tA1);
            tB1 = fma2(s1.x, mc, tB1); tB1 = fma2(s1.y, md, tB1);
        }
        accA0 = fma2(tA0, m1A, accA0);
        accA1 = fma2(tA1, m1A, accA1);
        accB0 = fma2(tB0, m1B, accB0);
        accB1 = fma2(tB1, m1B, accB1);
    }

    // out[b, kg*4 .. kg*4+3] : one 16B store per batch
    ulonglong2 oA; oA.x = accA0; oA.y = accA1;
    ulonglong2 oB; oB.x = accB0; oB.y = accB1;
    *reinterpret_cast<ulonglong2*>(out + (size_t)b0 * 32 + kg * 4) = oA;
    *reinterpret_cast<ulonglong2*>(out + (size_t)b1 * 32 + kg * 4) = oB;
}

// ---------------------------------------------------------------------------
extern "C" void kernel_launch(void* const* d_in, const int* in_sizes, int n_in,
                              void* d_out, int out_size)
{
    const float* X   = (const float*)d_in[0];
    const float* c11 = (const float*)d_in[1];
    const float* c12 = (const float*)d_in[2];
    const float* c13 = (const float*)d_in[3];
    const float* c14 = (const float*)d_in[4];
    const float* c21 = (const float*)d_in[5];
    const float* c22 = (const float*)d_in[6];
    const float* FM  = (const float*)d_in[7];
    const float* MT  = (const float*)d_in[8];
    (void)n_in; (void)out_size;

    int B = in_sizes[0] / 16;          // X is [B, 8, 2]
    int nbblk = B / (2 * BLOCK);       // 256 for B=65536

    precompute_S<<<32, 256>>>(c11, c12, c13, c14, c21, c22, FM, MT);
    tree_main<<<nbblk * 8, BLOCK>>>(X, (float*)d_out);
}